// round 15
// baseline (speedup 1.0000x reference)
#include <cuda_runtime.h>
#include <cuda_fp16.h>
#include <cstdint>
#include <math.h>

#define NB     32768
#define DMODEL 512
#define NHEADS 8
#define DHEAD  64

// GEMM tiling (R13 geometry)
#define BM 128
#define BN 128
#define BK 32                 // K halves (or floats) per stage
#define NSTAGE 6
#define STAGE_BYTES 32768     // A 16KB + B 16KB (128 rows x 128B each)
#define NKT 16                // DMODEL / BK

// ---------------------------------------------------------------------------
// Scratch buffers
// ---------------------------------------------------------------------------
__device__ float g_q1[(size_t)NB * DMODEL];
__device__ float g_k1[(size_t)NB * DMODEL];
__device__ float g_v1[(size_t)NB * DMODEL];
__device__ float g_q2[(size_t)NB * DMODEL];
__device__ float g_k2[(size_t)NB * DMODEL];
__device__ float g_v2[(size_t)NB * DMODEL];

__device__ __half g_o1_h[(size_t)NB * DMODEL];
__device__ __half g_o1_l[(size_t)NB * DMODEL];
__device__ __half g_o2_h[(size_t)NB * DMODEL];
__device__ __half g_o2_l[(size_t)NB * DMODEL];

// ---------------------------------------------------------------------------
// helpers
// ---------------------------------------------------------------------------
__device__ __forceinline__ uint32_t smem_u32(const void* p) {
    uint32_t a;
    asm("{ .reg .u64 t; cvta.to.shared.u64 t, %1; cvt.u32.u64 %0, t; }"
        : "=r"(a) : "l"(p));
    return a;
}
__device__ __forceinline__ void cp16(uint32_t dst, const void* src) {
    asm volatile("cp.async.cg.shared.global [%0], [%1], 16;" :: "r"(dst), "l"(src));
}
#define CP_COMMIT() asm volatile("cp.async.commit_group;" ::: "memory")
template <int N> __device__ __forceinline__ void cp_wait() {
    asm volatile("cp.async.wait_group %0;" :: "n"(N) : "memory");
}
#define CP_WAIT_ALL() asm volatile("cp.async.wait_all;" ::: "memory")

#define MBARRIER_INIT(addr, cnt) \
    asm volatile("mbarrier.init.shared.b64 [%0], %1;" :: "r"(addr), "r"(cnt) : "memory")
#define MBARRIER_ARRIVE(addr) \
    asm volatile("mbarrier.arrive.release.cta.shared.b64 _, [%0];" :: "r"(addr) : "memory")
#define CP_ASYNC_MBARRIER_ARRIVE(addr) \
    asm volatile("cp.async.mbarrier.arrive.noinc.shared.b64 [%0];" :: "r"(addr) : "memory")

#define MBARRIER_WAIT_PARITY(addr, parity) do {                                   \
    uint32_t _m = (addr); uint32_t _p = (parity); uint32_t _d;                    \
    asm volatile(                                                                 \
        "{\n\t.reg .pred p;\n\t"                                                  \
        "mbarrier.try_wait.parity.acquire.cta.shared::cta.b64 p, [%1], %2;\n\t"   \
        "selp.b32 %0, 1, 0, p;\n\t}"                                              \
        : "=r"(_d) : "r"(_m), "r"(_p) : "memory");                                \
    if (!_d) {                                                                    \
        asm volatile(                                                             \
            "{\n\t.reg .pred P1;\n\t"                                             \
            "WL_%=:\n\t"                                                          \
            "mbarrier.try_wait.parity.acquire.cta.shared::cta.b64 P1, [%0], %1, 0x989680;\n\t" \
            "@P1 bra.uni WD_%=;\n\t"                                              \
            "bra.uni WL_%=;\n\t"                                                  \
            "WD_%=:\n\t}"                                                         \
            :: "r"(_m), "r"(_p) : "memory");                                      \
    } } while (0)

#define STS64(addr, v0, v1) \
    asm volatile("st.shared.v2.b32 [%0], {%1,%2};" \
                 :: "r"(addr), "r"(v0), "r"(v1) : "memory")

__device__ __forceinline__ void ldm_x4(uint32_t* d, uint32_t addr) {
    asm volatile("ldmatrix.sync.aligned.m8n8.x4.shared.b16 {%0,%1,%2,%3}, [%4];"
                 : "=r"(d[0]), "=r"(d[1]), "=r"(d[2]), "=r"(d[3]) : "r"(addr));
}

__device__ __forceinline__ void mma_f16(float* d, const uint32_t* a, const uint32_t* b) {
    asm volatile(
        "mma.sync.aligned.m16n8k16.row.col.f32.f16.f16.f32 "
        "{%0,%1,%2,%3}, {%4,%5,%6,%7}, {%8,%9}, {%0,%1,%2,%3};"
        : "+f"(d[0]), "+f"(d[1]), "+f"(d[2]), "+f"(d[3])
        : "r"(a[0]), "r"(a[1]), "r"(a[2]), "r"(a[3]), "r"(b[0]), "r"(b[1]));
}

__device__ __forceinline__ uint32_t h2u(__half2 h) {
    return *(uint32_t*)&h;
}

// convert one float4 to hi/lo half2 pairs and STS.64 both into swizzled layout
__device__ __forceinline__ void split_sts(uint32_t st, int row, int c,
                                          const float4 a) {
    const int sw = row & 7;
    const __half2 h0 = __floats2half2_rn(a.x, a.y);
    const __half2 h1 = __floats2half2_rn(a.z, a.w);
    const float2 f0 = __half22float2(h0), f1 = __half22float2(h1);
    const __half2 l0 = __floats2half2_rn(a.x - f0.x, a.y - f0.y);
    const __half2 l1 = __floats2half2_rn(a.z - f1.x, a.w - f1.y);
    const uint32_t rowb = st + row * 128 + ((c & 1) << 3);
    STS64(rowb + ((((c >> 1)    ) ^ sw) << 4), h2u(h0), h2u(h1));
    STS64(rowb + ((((c >> 1) + 4) ^ sw) << 4), h2u(l0), h2u(l1));
}

// ---------------------------------------------------------------------------
// Warp-specialized split-fp16 GEMM: C = X @ W^T + bias
//   B (weights) always fp32-fused: producers LDG fp32 W, split hi/lo, STS.
//   FUSE_SPLIT_A=true : A also fp32-fused (proj GEMM).
//   FUSE_SPLIT_A=false: A pre-split fp16 via cp.async (out GEMM).
// ---------------------------------------------------------------------------
struct GemmBatch {
    const float*  Xf[6];
    const __half* Xh[6];
    const __half* Xl[6];
    const float*  Wf[6];
    const float*  bias[6];
    float*        C[6];
};

template <bool FUSE_SPLIT_A>
__global__ __launch_bounds__(384, 1)
void gemm_mma_kernel(GemmBatch args)
{
    const int z = blockIdx.z;
    const float*  __restrict__ bias = args.bias[z];
    float*        __restrict__ C    = args.C[z];

    const int n0 = blockIdx.x * BN;
    const int m0 = blockIdx.y * BM;

    extern __shared__ __align__(128) char smraw[];
    const uint32_t sbase = smem_u32(smraw);

    __shared__ __align__(8) uint64_t s_full_b[NSTAGE], s_full_a[NSTAGE], s_empty[NSTAGE];

    const int tid  = threadIdx.x;
    const int wid  = tid >> 5;
    const int lane = tid & 31;

    if (tid == 0) {
#pragma unroll
        for (int s = 0; s < NSTAGE; ++s) {
            MBARRIER_INIT(smem_u32(&s_full_b[s]), 128);   // cp.async noinc (non-FUSE A)
            MBARRIER_INIT(smem_u32(&s_full_a[s]), 128);   // STS thread arrives
            MBARRIER_INIT(smem_u32(&s_empty[s]), 8);
        }
    }
    __syncthreads();

    if (wid >= 8) {
        // ================= PRODUCER (warps 8-11, 128 threads) =================
        const float* __restrict__ Wf = args.Wf[z];
        const int ptid = tid - 256;   // 0..127

        if (FUSE_SPLIT_A) {
            const float* __restrict__ Xf = args.Xf[z];
#pragma unroll
            for (int kt = 0; kt < NKT; ++kt) {
                const int s = kt % NSTAGE;
                // hoist A LDGs (coalesced: 8 thr/row, consecutive 16B)
                float4 av[8];
#pragma unroll
                for (int j = 0; j < 8; ++j) {
                    const int idx = ptid + j * 128;
                    const int row = idx >> 3, c = idx & 7;
                    av[j] = *(const float4*)(Xf + (size_t)(m0 + row) * DMODEL
                                             + kt * BK + c * 4);
                }
                if (kt >= NSTAGE) {
                    MBARRIER_WAIT_PARITY(smem_u32(&s_empty[s]),
                                         (uint32_t)(((kt - NSTAGE) / NSTAGE) & 1));
                }
                const uint32_t st = sbase + s * STAGE_BYTES;

                // A: convert + STS
#pragma unroll
                for (int j = 0; j < 8; ++j) {
                    const int idx = ptid + j * 128;
                    split_sts(st, idx >> 3, idx & 7, av[j]);
                }
                // B: LDG fp32 W (coalesced), convert + STS at st+16384
#pragma unroll
                for (int j = 0; j < 8; ++j) {
                    const int idx = ptid + j * 128;
                    const int row = idx >> 3, c = idx & 7;
                    av[j] = *(const float4*)(Wf + (size_t)(n0 + row) * DMODEL
                                             + kt * BK + c * 4);
                }
#pragma unroll
                for (int j = 0; j < 8; ++j) {
                    const int idx = ptid + j * 128;
                    split_sts(st + 16384, idx >> 3, idx & 7, av[j]);
                }
                MBARRIER_ARRIVE(smem_u32(&s_full_a[s]));   // release: all STS visible
            }
        } else {
            const __half* __restrict__ Xh = args.Xh[z];
            const __half* __restrict__ Xl = args.Xl[z];
#pragma unroll
            for (int kt = 0; kt < NKT; ++kt) {
                const int s = kt % NSTAGE;
                // hoist B LDGs (fp32 W, coalesced)
                float4 bv[8];
#pragma unroll
                for (int j = 0; j < 8; ++j) {
                    const int idx = ptid + j * 128;
                    const int row = idx >> 3, c = idx & 7;
                    bv[j] = *(const float4*)(Wf + (size_t)(n0 + row) * DMODEL
                                             + kt * BK + c * 4);
                }
                if (kt >= NSTAGE) {
                    MBARRIER_WAIT_PARITY(smem_u32(&s_empty[s]),
                                         (uint32_t)(((kt - NSTAGE) / NSTAGE) & 1));
                }
                const uint32_t st = sbase + s * STAGE_BYTES;
                const size_t koff = (size_t)kt * BK;

                // A via cp.async (pre-split hi/lo from attention)
#pragma unroll
                for (int j = 0; j < 8; ++j) {
                    const int idx = ptid + j * 128;
                    const int row = idx >> 3, c = idx & 7;
                    const __half* src = (c < 4) ? Xh : Xl;
                    cp16(st + row * 128 + ((c ^ (row & 7)) << 4),
                         src + (size_t)(m0 + row) * DMODEL + koff + (c & 3) * 8);
                }
                CP_ASYNC_MBARRIER_ARRIVE(smem_u32(&s_full_b[s]));

                // B: convert + STS
#pragma unroll
                for (int j = 0; j < 8; ++j) {
                    const int idx = ptid + j * 128;
                    split_sts(st + 16384, idx >> 3, idx & 7, bv[j]);
                }
                MBARRIER_ARRIVE(smem_u32(&s_full_a[s]));
            }
        }
        CP_WAIT_ALL();
        return;
    }

    // =================== CONSUMER (warps 0-7, 256 threads) ===================
    const int r  = lane >> 2;
    const int cq = lane & 3;
    const int wm = (wid >> 1) * 32;
    const int wn = (wid & 1) * 64;

    const int a_row_in16 = (lane & 7) + ((lane >> 3) & 1) * 8;
    const int a_kh       = lane >> 4;
    const int b_row_in16 = (lane & 7) + ((lane >> 4) & 1) * 8;
    const int b_kh       = (lane >> 3) & 1;

    float acc[2][8][4];
#pragma unroll
    for (int i = 0; i < 2; ++i)
#pragma unroll
        for (int j = 0; j < 8; ++j)
#pragma unroll
            for (int k = 0; k < 4; ++k)
                acc[i][j][k] = 0.f;

#define LOAD_BFRAGS(bu, ksv, grpv) do {                                         \
        _Pragma("unroll")                                                       \
        for (int pair = 0; pair < 2; ++pair) {                                  \
            const int brow = wn + (grpv) * 32 + pair * 16 + b_row_in16;         \
            const int sw = brow & 7;                                            \
            const uint32_t rb = bB + brow * 128;                                \
            uint32_t th[4], tl[4];                                              \
            ldm_x4(th, rb + (((2 * (ksv) + b_kh) ^ sw) << 4));                  \
            ldm_x4(tl, rb + (((2 * (ksv) + b_kh + 4) ^ sw) << 4));              \
            bhb[bu][pair * 2 + 0][0] = th[0]; bhb[bu][pair * 2 + 0][1] = th[1]; \
            bhb[bu][pair * 2 + 1][0] = th[2]; bhb[bu][pair * 2 + 1][1] = th[3]; \
            blb[bu][pair * 2 + 0][0] = tl[0]; blb[bu][pair * 2 + 0][1] = tl[1]; \
            blb[bu][pair * 2 + 1][0] = tl[2]; blb[bu][pair * 2 + 1][1] = tl[3]; \
        }                                                                       \
    } while (0)

#define MMA_GROUP(bu, grpv) do {                                                \
        _Pragma("unroll")                                                       \
        for (int i = 0; i < 4; ++i) {                                           \
            mma_f16(acc[0][(grpv) * 4 + i], ah[0], bhb[bu][i]);                 \
            mma_f16(acc[1][(grpv) * 4 + i], ah[1], bhb[bu][i]);                 \
        }                                                                       \
        _Pragma("unroll")                                                       \
        for (int i = 0; i < 4; ++i) {                                           \
            mma_f16(acc[0][(grpv) * 4 + i], ah[0], blb[bu][i]);                 \
            mma_f16(acc[1][(grpv) * 4 + i], ah[1], blb[bu][i]);                 \
        }                                                                       \
        _Pragma("unroll")                                                       \
        for (int i = 0; i < 4; ++i) {                                           \
            mma_f16(acc[0][(grpv) * 4 + i], al[0], bhb[bu][i]);                 \
            mma_f16(acc[1][(grpv) * 4 + i], al[1], bhb[bu][i]);                 \
        }                                                                       \
    } while (0)

#define LOAD_AFRAGS(ksv) do {                                                   \
        _Pragma("unroll")                                                       \
        for (int ma = 0; ma < 2; ++ma) {                                        \
            const int arow = wm + ma * 16 + a_row_in16;                         \
            const int sw = arow & 7;                                            \
            const uint32_t rb = aB + arow * 128;                                \
            ldm_x4(ah[ma], rb + (((2 * (ksv) + a_kh) ^ sw) << 4));              \
            ldm_x4(al[ma], rb + (((2 * (ksv) + a_kh + 4) ^ sw) << 4));          \
        }                                                                       \
    } while (0)

    uint32_t bhb[2][4][2], blb[2][4][2];
    uint32_t ah[2][4], al[2][4];

#pragma unroll
    for (int kt = 0; kt < NKT; ++kt) {
        const int s = kt % NSTAGE;
        const uint32_t ph = (uint32_t)((kt / NSTAGE) & 1);
        if (!FUSE_SPLIT_A)
            MBARRIER_WAIT_PARITY(smem_u32(&s_full_b[s]), ph);   // A via cp.async
        MBARRIER_WAIT_PARITY(smem_u32(&s_full_a[s]), ph);       // STS operands

        const uint32_t aB = sbase + s * STAGE_BYTES;
        const uint32_t bB = aB + 16384;

        LOAD_AFRAGS(0);
        LOAD_BFRAGS(0, 0, 0);
        LOAD_BFRAGS(1, 0, 1);
        MMA_GROUP(0, 0);
        LOAD_BFRAGS(0, 1, 0);
        MMA_GROUP(1, 1);
        LOAD_AFRAGS(1);
        LOAD_BFRAGS(1, 1, 1);
        MMA_GROUP(0, 0);
        MMA_GROUP(1, 1);

        if (lane == 0) MBARRIER_ARRIVE(smem_u32(&s_empty[s]));
    }
#undef LOAD_BFRAGS
#undef MMA_GROUP
#undef LOAD_AFRAGS

    // epilogue
#pragma unroll
    for (int j = 0; j < 8; ++j) {
        const int col = n0 + wn + (j >> 2) * 32 + (j & 3) * 8 + 2 * cq;
        const float2 bv = *(const float2*)(bias + col);
#pragma unroll
        for (int ma = 0; ma < 2; ++ma) {
            const int row = m0 + wm + ma * 16 + r;
            float2 v0, v1;
            v0.x = acc[ma][j][0] + bv.x;
            v0.y = acc[ma][j][1] + bv.y;
            v1.x = acc[ma][j][2] + bv.x;
            v1.y = acc[ma][j][3] + bv.y;
            *(float2*)(C + (size_t)row * DMODEL + col)       = v0;
            *(float2*)(C + (size_t)(row + 8) * DMODEL + col) = v1;
        }
    }
}

// ---------------------------------------------------------------------------
// Attention (near bandwidth bound, unchanged)
// ---------------------------------------------------------------------------
#define AW 8
__global__ __launch_bounds__(32 * AW)
void attention_kernel(const float* __restrict__ q1, const float* __restrict__ k1,
                      const float* __restrict__ v1, const float* __restrict__ q2,
                      const float* __restrict__ k2, const float* __restrict__ v2,
                      __half* __restrict__ o1h, __half* __restrict__ o1l,
                      __half* __restrict__ o2h, __half* __restrict__ o2l)
{
    __shared__ float sq[2][AW][NHEADS][68];
    __shared__ float sk[2][AW][NHEADS][68];
    __shared__ float sv[2][AW][NHEADS][68];
    __shared__ float ss[AW][NHEADS][NHEADS];

    const int w = threadIdx.x >> 5;
    const int l = threadIdx.x & 31;
    const int s = blockIdx.x * AW + w;

    const float* Q[2] = { q1 + (size_t)s * DMODEL, q2 + (size_t)s * DMODEL };
    const float* K[2] = { k1 + (size_t)s * DMODEL, k2 + (size_t)s * DMODEL };
    const float* V[2] = { v1 + (size_t)s * DMODEL, v2 + (size_t)s * DMODEL };
    __half* OH[2] = { o1h + (size_t)s * DMODEL, o2h + (size_t)s * DMODEL };
    __half* OL[2] = { o1l + (size_t)s * DMODEL, o2l + (size_t)s * DMODEL };

    const int h0 = l >> 3;
    const int e0 = l & 7;

#pragma unroll
    for (int side = 0; side < 2; ++side) {
#pragma unroll
        for (int i = 0; i < 4; ++i) {
            const int idx = i * 32 + l;
            const int h = idx >> 4;
            const int d = (idx & 15) * 4;
            cp16(smem_u32(&sq[side][w][h][d]), Q[side] + idx * 4);
            cp16(smem_u32(&sk[side][w][h][d]), K[side] + idx * 4);
            cp16(smem_u32(&sv[side][w][h][d]), V[side] + idx * 4);
        }
        CP_COMMIT();
    }

#pragma unroll
    for (int side = 0; side < 2; ++side) {
        if (side == 0) cp_wait<1>(); else cp_wait<0>();
        __syncwarp();

        float s0 = 0.f, s1 = 0.f;
#pragma unroll
        for (int d4 = 0; d4 < 16; ++d4) {
            const float4 kk = *(const float4*)&sk[side][w][e0][d4 * 4];
            const float4 qa = *(const float4*)&sq[side][w][h0][d4 * 4];
            const float4 qb = *(const float4*)&sq[side][w][h0 + 4][d4 * 4];
            s0 = fmaf(qa.x, kk.x, s0); s0 = fmaf(qa.y, kk.y, s0);
            s0 = fmaf(qa.z, kk.z, s0); s0 = fmaf(qa.w, kk.w, s0);
            s1 = fmaf(qb.x, kk.x, s1); s1 = fmaf(qb.y, kk.y, s1);
            s1 = fmaf(qb.z, kk.z, s1); s1 = fmaf(qb.w, kk.w, s1);
        }
        s0 *= 0.125f;
        s1 *= 0.125f;

        float m0 = s0, m1 = s1;
#pragma unroll
        for (int d = 1; d < 8; d <<= 1) {
            m0 = fmaxf(m0, __shfl_xor_sync(0xFFFFFFFF, m0, d));
            m1 = fmaxf(m1, __shfl_xor_sync(0xFFFFFFFF, m1, d));
        }
        float x0 = expf(s0 - m0), x1 = expf(s1 - m1);
        float sum0 = x0, sum1 = x1;
#pragma unroll
        for (int d = 1; d < 8; d <<= 1) {
            sum0 += __shfl_xor_sync(0xFFFFFFFF, sum0, d);
            sum1 += __shfl_xor_sync(0xFFFFFFFF, sum1, d);
        }
        ss[w][h0][e0]     = x0 / sum0;
        ss[w][h0 + 4][e0] = x1 / sum1;
        __syncwarp();

#pragma unroll
        for (int dd = 0; dd < 2; ++dd) {
            const int d = l + dd * 32;
#pragma unroll
            for (int h = 0; h < NHEADS; ++h) {
                float a = 0.f;
#pragma unroll
                for (int e = 0; e < NHEADS; ++e)
                    a = fmaf(ss[w][h][e], sv[side][w][e][d], a);
                sq[side][w][h][d] = a;
            }
        }
        __syncwarp();

        __half2* oh2 = (__half2*)OH[side];
        __half2* ol2 = (__half2*)OL[side];
#pragma unroll
        for (int i = 0; i < 8; ++i) {
            const int j = i * 32 + l;
            const int h = j >> 5;
            const int d = (j & 31) * 2;
            const float a = sq[side][w][h][d];
            const float b = sq[side][w][h][d + 1];
            const __half2 hv = __floats2half2_rn(a, b);
            const float2 hf = __half22float2(hv);
            const __half2 lv = __floats2half2_rn(a - hf.x, b - hf.y);
            oh2[j] = hv;
            ol2[j] = lv;
        }
        __syncwarp();
    }
}

// ---------------------------------------------------------------------------
// kernel_launch
// ---------------------------------------------------------------------------
extern "C" void kernel_launch(void* const* d_in, const int* in_sizes, int n_in,
                              void* d_out, int out_size)
{
    const float* prot = (const float*)d_in[0];
    const float* lig  = (const float*)d_in[1];
    const float* Wq1 = (const float*)d_in[2];  const float* bq1 = (const float*)d_in[3];
    const float* Wk1 = (const float*)d_in[4];  const float* bk1 = (const float*)d_in[5];
    const float* Wv1 = (const float*)d_in[6];  const float* bv1 = (const float*)d_in[7];
    const float* Wq2 = (const float*)d_in[8];  const float* bq2 = (const float*)d_in[9];
    const float* Wk2 = (const float*)d_in[10]; const float* bk2 = (const float*)d_in[11];
    const float* Wv2 = (const float*)d_in[12]; const float* bv2 = (const float*)d_in[13];
    const float* Wo1 = (const float*)d_in[14]; const float* bo1 = (const float*)d_in[15];
    const float* Wo2 = (const float*)d_in[16]; const float* bo2 = (const float*)d_in[17];

    float* out      = (float*)d_out;
    float* prot_out = out;
    float* lig_out  = out + (size_t)NB * DMODEL;

    float *q1, *k1, *v1, *q2, *k2, *v2;
    cudaGetSymbolAddress((void**)&q1, g_q1);
    cudaGetSymbolAddress((void**)&k1, g_k1);
    cudaGetSymbolAddress((void**)&v1, g_v1);
    cudaGetSymbolAddress((void**)&q2, g_q2);
    cudaGetSymbolAddress((void**)&k2, g_k2);
    cudaGetSymbolAddress((void**)&v2, g_v2);

    __half *o1h, *o1l, *o2h, *o2l;
    cudaGetSymbolAddress((void**)&o1h, g_o1_h);
    cudaGetSymbolAddress((void**)&o1l, g_o1_l);
    cudaGetSymbolAddress((void**)&o2h, g_o2_h);
    cudaGetSymbolAddress((void**)&o2l, g_o2_l);

    const int DSM = NSTAGE * STAGE_BYTES;   // 196608
    cudaFuncSetAttribute(gemm_mma_kernel<true>,
                         cudaFuncAttributeMaxDynamicSharedMemorySize, DSM);
    cudaFuncSetAttribute(gemm_mma_kernel<false>,
                         cudaFuncAttributeMaxDynamicSharedMemorySize, DSM);

    // six input projections: A = fp32 inputs, W = fp32 weights, both fused
    GemmBatch pj = {};
    pj.Xf[0] = prot; pj.Wf[0] = Wq1; pj.bias[0] = bq1; pj.C[0] = q1;
    pj.Xf[1] = lig;  pj.Wf[1] = Wk1; pj.bias[1] = bk1; pj.C[1] = k1;
    pj.Xf[2] = lig;  pj.Wf[2] = Wv1; pj.bias[2] = bv1; pj.C[2] = v1;
    pj.Xf[3] = lig;  pj.Wf[3] = Wq2; pj.bias[3] = bq2; pj.C[3] = q2;
    pj.Xf[4] = prot; pj.Wf[4] = Wk2; pj.bias[4] = bk2; pj.C[4] = k2;
    pj.Xf[5] = prot; pj.Wf[5] = Wv2; pj.bias[5] = bv2; pj.C[5] = v2;

    dim3 gproj(DMODEL / BN, NB / BM, 6);
    gemm_mma_kernel<true><<<gproj, 384, DSM>>>(pj);

    attention_kernel<<<NB / AW, 32 * AW>>>(q1, k1, v1, q2, k2, v2, o1h, o1l, o2h, o2l);

    // output projections: A = attention hi/lo (pre-split), W = fp32 fused
    GemmBatch op = {};
    op.Xh[0] = o1h; op.Xl[0] = o1l; op.Wf[0] = Wo1; op.bias[0] = bo1; op.C[0] = prot_out;
    op.Xh[1] = o2h; op.Xl[1] = o2l; op.Wf[1] = Wo2; op.bias[1] = bo2; op.C[1] = lig_out;
    for (int i = 2; i < 6; ++i) {
        op.Xh[i] = o1h; op.Xl[i] = o1l; op.Wf[i] = Wo1;
        op.bias[i] = bo1; op.C[i] = prot_out;
    }

    dim3 gout(DMODEL / BN, NB / BM, 2);
    gemm_mma_kernel<false><<<gout, 384, DSM>>>(op);
}

// round 16
// speedup vs baseline: 1.3396x; 1.3396x over previous
#include <cuda_runtime.h>
#include <cuda_fp16.h>
#include <cstdint>
#include <math.h>

#define NB     32768
#define DMODEL 512
#define NHEADS 8
#define DHEAD  64

// GEMM tiling (R13 geometry — best known)
#define BM 128
#define BN 128
#define BK 32                 // K halves (or floats) per stage
#define NSTAGE 6
#define STAGE_BYTES 32768     // A 16KB + B 16KB (128 rows x 128B each)
#define NKT 16                // DMODEL / BK

// ---------------------------------------------------------------------------
// Scratch buffers
// ---------------------------------------------------------------------------
__device__ float g_q1[(size_t)NB * DMODEL];
__device__ float g_k1[(size_t)NB * DMODEL];
__device__ float g_v1[(size_t)NB * DMODEL];
__device__ float g_q2[(size_t)NB * DMODEL];
__device__ float g_k2[(size_t)NB * DMODEL];
__device__ float g_v2[(size_t)NB * DMODEL];

__device__ __half g_o1_h[(size_t)NB * DMODEL];
__device__ __half g_o1_l[(size_t)NB * DMODEL];
__device__ __half g_o2_h[(size_t)NB * DMODEL];
__device__ __half g_o2_l[(size_t)NB * DMODEL];
__device__ __half g_W_h[8][DMODEL * DMODEL];
__device__ __half g_W_l[8][DMODEL * DMODEL];

// ---------------------------------------------------------------------------
// helpers
// ---------------------------------------------------------------------------
__device__ __forceinline__ uint32_t smem_u32(const void* p) {
    uint32_t a;
    asm("{ .reg .u64 t; cvta.to.shared.u64 t, %1; cvt.u32.u64 %0, t; }"
        : "=r"(a) : "l"(p));
    return a;
}
__device__ __forceinline__ void cp16(uint32_t dst, const void* src) {
    asm volatile("cp.async.cg.shared.global [%0], [%1], 16;" :: "r"(dst), "l"(src));
}
#define CP_COMMIT() asm volatile("cp.async.commit_group;" ::: "memory")
template <int N> __device__ __forceinline__ void cp_wait() {
    asm volatile("cp.async.wait_group %0;" :: "n"(N) : "memory");
}
#define CP_WAIT_ALL() asm volatile("cp.async.wait_all;" ::: "memory")

#define MBARRIER_INIT(addr, cnt) \
    asm volatile("mbarrier.init.shared.b64 [%0], %1;" :: "r"(addr), "r"(cnt) : "memory")
#define MBARRIER_ARRIVE(addr) \
    asm volatile("mbarrier.arrive.release.cta.shared.b64 _, [%0];" :: "r"(addr) : "memory")
#define CP_ASYNC_MBARRIER_ARRIVE(addr) \
    asm volatile("cp.async.mbarrier.arrive.noinc.shared.b64 [%0];" :: "r"(addr) : "memory")

#define MBARRIER_WAIT_PARITY(addr, parity) do {                                   \
    uint32_t _m = (addr); uint32_t _p = (parity); uint32_t _d;                    \
    asm volatile(                                                                 \
        "{\n\t.reg .pred p;\n\t"                                                  \
        "mbarrier.try_wait.parity.acquire.cta.shared::cta.b64 p, [%1], %2;\n\t"   \
        "selp.b32 %0, 1, 0, p;\n\t}"                                              \
        : "=r"(_d) : "r"(_m), "r"(_p) : "memory");                                \
    if (!_d) {                                                                    \
        asm volatile(                                                             \
            "{\n\t.reg .pred P1;\n\t"                                             \
            "WL_%=:\n\t"                                                          \
            "mbarrier.try_wait.parity.acquire.cta.shared::cta.b64 P1, [%0], %1, 0x989680;\n\t" \
            "@P1 bra.uni WD_%=;\n\t"                                              \
            "bra.uni WL_%=;\n\t"                                                  \
            "WD_%=:\n\t}"                                                         \
            :: "r"(_m), "r"(_p) : "memory");                                      \
    } } while (0)

#define STS64(addr, v0, v1) \
    asm volatile("st.shared.v2.b32 [%0], {%1,%2};" \
                 :: "r"(addr), "r"(v0), "r"(v1) : "memory")

__device__ __forceinline__ void ldm_x4(uint32_t* d, uint32_t addr) {
    asm volatile("ldmatrix.sync.aligned.m8n8.x4.shared.b16 {%0,%1,%2,%3}, [%4];"
                 : "=r"(d[0]), "=r"(d[1]), "=r"(d[2]), "=r"(d[3]) : "r"(addr));
}

__device__ __forceinline__ void mma_f16(float* d, const uint32_t* a, const uint32_t* b) {
    asm volatile(
        "mma.sync.aligned.m16n8k16.row.col.f32.f16.f16.f32 "
        "{%0,%1,%2,%3}, {%4,%5,%6,%7}, {%8,%9}, {%0,%1,%2,%3};"
        : "+f"(d[0]), "+f"(d[1]), "+f"(d[2]), "+f"(d[3])
        : "r"(a[0]), "r"(a[1]), "r"(a[2]), "r"(a[3]), "r"(b[0]), "r"(b[1]));
}

__device__ __forceinline__ uint32_t h2u(__half2 h) {
    return *(uint32_t*)&h;
}

// ---------------------------------------------------------------------------
// Weight split kernel (weights reused 256x -> pre-split via cp-friendly path)
// ---------------------------------------------------------------------------
struct WSplit { const float* src[8]; };

__global__ __launch_bounds__(256)
void split_w_kernel(WSplit ws)
{
    const int z = blockIdx.y;
    const float2* src = (const float2*)ws.src[z];
    __half2* hi = (__half2*)&g_W_h[z][0];
    __half2* lo = (__half2*)&g_W_l[z][0];
    const int n2 = DMODEL * DMODEL / 2;
    for (int i = blockIdx.x * blockDim.x + threadIdx.x; i < n2;
         i += gridDim.x * blockDim.x) {
        float2 v = src[i];
        __half2 h = __floats2half2_rn(v.x, v.y);
        float2 hb = __half22float2(h);
        __half2 l = __floats2half2_rn(v.x - hb.x, v.y - hb.y);
        hi[i] = h;
        lo[i] = l;
    }
}

// ---------------------------------------------------------------------------
// Warp-specialized split-fp16 GEMM (R13): C = X @ W^T + bias
//   FUSE_SPLIT_A=true : A fp32, split in producers (coalesced LDG + STS).
//   FUSE_SPLIT_A=false: A pre-split fp16 via cp.async.
//   B always pre-split fp16 via cp.async.
//   Consumer arrives `empty` right after its LAST ldmatrix of the stage
//   (release orders the reads) — producers refill earlier.
// ---------------------------------------------------------------------------
struct GemmBatch {
    const float*  Xf[6];
    const __half* Xh[6];
    const __half* Xl[6];
    const __half* Wh[6];
    const __half* Wl[6];
    const float*  bias[6];
    float*        C[6];
};

template <bool FUSE_SPLIT_A>
__global__ __launch_bounds__(384, 1)
void gemm_mma_kernel(GemmBatch args)
{
    const int z = blockIdx.z;
    const float*  __restrict__ bias = args.bias[z];
    float*        __restrict__ C    = args.C[z];

    const int n0 = blockIdx.x * BN;
    const int m0 = blockIdx.y * BM;

    extern __shared__ __align__(128) char smraw[];
    const uint32_t sbase = smem_u32(smraw);

    __shared__ __align__(8) uint64_t s_full_b[NSTAGE], s_full_a[NSTAGE], s_empty[NSTAGE];

    const int tid  = threadIdx.x;
    const int wid  = tid >> 5;
    const int lane = tid & 31;

    if (tid == 0) {
#pragma unroll
        for (int s = 0; s < NSTAGE; ++s) {
            MBARRIER_INIT(smem_u32(&s_full_b[s]), 128);
            MBARRIER_INIT(smem_u32(&s_full_a[s]), 128);
            MBARRIER_INIT(smem_u32(&s_empty[s]), 8);
        }
    }
    __syncthreads();

    if (wid >= 8) {
        // ================= PRODUCER (warps 8-11, 128 threads) =================
        const __half* __restrict__ Wh = args.Wh[z];
        const __half* __restrict__ Wl = args.Wl[z];
        const int ptid = tid - 256;   // 0..127

        if (FUSE_SPLIT_A) {
            const float* __restrict__ Xf = args.Xf[z];
#pragma unroll
            for (int kt = 0; kt < NKT; ++kt) {
                const int s = kt % NSTAGE;
                // coalesced A loads: 8 thr/row, consecutive 16B chunks
                float4 av[8];
#pragma unroll
                for (int j = 0; j < 8; ++j) {
                    const int idx = ptid + j * 128;
                    const int row = idx >> 3, c = idx & 7;
                    av[j] = *(const float4*)(Xf + (size_t)(m0 + row) * DMODEL
                                             + kt * BK + c * 4);
                }
                if (kt >= NSTAGE) {
                    MBARRIER_WAIT_PARITY(smem_u32(&s_empty[s]),
                                         (uint32_t)(((kt - NSTAGE) / NSTAGE) & 1));
                }
                const uint32_t st = sbase + s * STAGE_BYTES;
                const size_t koff = (size_t)kt * BK;

                // B via cp.async
#pragma unroll
                for (int j = 0; j < 8; ++j) {
                    const int idx = ptid + j * 128;
                    const int row = idx >> 3, c = idx & 7;
                    const __half* src = (c < 4) ? Wh : Wl;
                    cp16(st + 16384 + row * 128 + ((c ^ (row & 7)) << 4),
                         src + (size_t)(n0 + row) * DMODEL + koff + (c & 3) * 8);
                }
                CP_ASYNC_MBARRIER_ARRIVE(smem_u32(&s_full_b[s]));

                // A: convert fp32 -> hi/lo, STS.64 into swizzled layout
#pragma unroll
                for (int j = 0; j < 8; ++j) {
                    const int idx = ptid + j * 128;
                    const int row = idx >> 3, c = idx & 7;
                    const int sw = row & 7;
                    const float4 a = av[j];
                    const __half2 h0 = __floats2half2_rn(a.x, a.y);
                    const __half2 h1 = __floats2half2_rn(a.z, a.w);
                    const float2 f0 = __half22float2(h0), f1 = __half22float2(h1);
                    const __half2 l0 = __floats2half2_rn(a.x - f0.x, a.y - f0.y);
                    const __half2 l1 = __floats2half2_rn(a.z - f1.x, a.w - f1.y);
                    const uint32_t rowb = st + row * 128 + ((c & 1) << 3);
                    STS64(rowb + ((((c >> 1)    ) ^ sw) << 4), h2u(h0), h2u(h1));
                    STS64(rowb + ((((c >> 1) + 4) ^ sw) << 4), h2u(l0), h2u(l1));
                }
                MBARRIER_ARRIVE(smem_u32(&s_full_a[s]));
            }
        } else {
            const __half* __restrict__ Xh = args.Xh[z];
            const __half* __restrict__ Xl = args.Xl[z];
#pragma unroll
            for (int kt = 0; kt < NKT; ++kt) {
                const int s = kt % NSTAGE;
                if (kt >= NSTAGE) {
                    MBARRIER_WAIT_PARITY(smem_u32(&s_empty[s]),
                                         (uint32_t)(((kt - NSTAGE) / NSTAGE) & 1));
                }
                const uint32_t st = sbase + s * STAGE_BYTES;
                const size_t koff = (size_t)kt * BK;
#pragma unroll
                for (int j = 0; j < 8; ++j) {
                    const int idx = ptid + j * 128;
                    const int row = idx >> 3, c = idx & 7;
                    const __half* src = (c < 4) ? Xh : Xl;
                    cp16(st + row * 128 + ((c ^ (row & 7)) << 4),
                         src + (size_t)(m0 + row) * DMODEL + koff + (c & 3) * 8);
                }
#pragma unroll
                for (int j = 0; j < 8; ++j) {
                    const int idx = ptid + j * 128;
                    const int row = idx >> 3, c = idx & 7;
                    const __half* src = (c < 4) ? Wh : Wl;
                    cp16(st + 16384 + row * 128 + ((c ^ (row & 7)) << 4),
                         src + (size_t)(n0 + row) * DMODEL + koff + (c & 3) * 8);
                }
                CP_ASYNC_MBARRIER_ARRIVE(smem_u32(&s_full_b[s]));
            }
        }
        CP_WAIT_ALL();
        return;
    }

    // =================== CONSUMER (warps 0-7, 256 threads) ===================
    const int r  = lane >> 2;
    const int cq = lane & 3;
    const int wm = (wid >> 1) * 32;
    const int wn = (wid & 1) * 64;

    const int a_row_in16 = (lane & 7) + ((lane >> 3) & 1) * 8;
    const int a_kh       = lane >> 4;
    const int b_row_in16 = (lane & 7) + ((lane >> 4) & 1) * 8;
    const int b_kh       = (lane >> 3) & 1;

    float acc[2][8][4];
#pragma unroll
    for (int i = 0; i < 2; ++i)
#pragma unroll
        for (int j = 0; j < 8; ++j)
#pragma unroll
            for (int k = 0; k < 4; ++k)
                acc[i][j][k] = 0.f;

#define LOAD_BFRAGS(bu, ksv, grpv) do {                                         \
        _Pragma("unroll")                                                       \
        for (int pair = 0; pair < 2; ++pair) {                                  \
            const int brow = wn + (grpv) * 32 + pair * 16 + b_row_in16;         \
            const int sw = brow & 7;                                            \
            const uint32_t rb = bB + brow * 128;                                \
            uint32_t th[4], tl[4];                                              \
            ldm_x4(th, rb + (((2 * (ksv) + b_kh) ^ sw) << 4));                  \
            ldm_x4(tl, rb + (((2 * (ksv) + b_kh + 4) ^ sw) << 4));              \
            bhb[bu][pair * 2 + 0][0] = th[0]; bhb[bu][pair * 2 + 0][1] = th[1]; \
            bhb[bu][pair * 2 + 1][0] = th[2]; bhb[bu][pair * 2 + 1][1] = th[3]; \
            blb[bu][pair * 2 + 0][0] = tl[0]; blb[bu][pair * 2 + 0][1] = tl[1]; \
            blb[bu][pair * 2 + 1][0] = tl[2]; blb[bu][pair * 2 + 1][1] = tl[3]; \
        }                                                                       \
    } while (0)

#define MMA_GROUP(bu, grpv) do {                                                \
        _Pragma("unroll")                                                       \
        for (int i = 0; i < 4; ++i) {                                           \
            mma_f16(acc[0][(grpv) * 4 + i], ah[0], bhb[bu][i]);                 \
            mma_f16(acc[1][(grpv) * 4 + i], ah[1], bhb[bu][i]);                 \
        }                                                                       \
        _Pragma("unroll")                                                       \
        for (int i = 0; i < 4; ++i) {                                           \
            mma_f16(acc[0][(grpv) * 4 + i], ah[0], blb[bu][i]);                 \
            mma_f16(acc[1][(grpv) * 4 + i], ah[1], blb[bu][i]);                 \
        }                                                                       \
        _Pragma("unroll")                                                       \
        for (int i = 0; i < 4; ++i) {                                           \
            mma_f16(acc[0][(grpv) * 4 + i], al[0], bhb[bu][i]);                 \
            mma_f16(acc[1][(grpv) * 4 + i], al[1], bhb[bu][i]);                 \
        }                                                                       \
    } while (0)

#define LOAD_AFRAGS(ksv) do {                                                   \
        _Pragma("unroll")                                                       \
        for (int ma = 0; ma < 2; ++ma) {                                        \
            const int arow = wm + ma * 16 + a_row_in16;                         \
            const int sw = arow & 7;                                            \
            const uint32_t rb = aB + arow * 128;                                \
            ldm_x4(ah[ma], rb + (((2 * (ksv) + a_kh) ^ sw) << 4));              \
            ldm_x4(al[ma], rb + (((2 * (ksv) + a_kh + 4) ^ sw) << 4));          \
        }                                                                       \
    } while (0)

    uint32_t bhb[2][4][2], blb[2][4][2];
    uint32_t ah[2][4], al[2][4];

#pragma unroll
    for (int kt = 0; kt < NKT; ++kt) {
        const int s = kt % NSTAGE;
        const uint32_t ph = (uint32_t)((kt / NSTAGE) & 1);
        MBARRIER_WAIT_PARITY(smem_u32(&s_full_b[s]), ph);
        if (FUSE_SPLIT_A)
            MBARRIER_WAIT_PARITY(smem_u32(&s_full_a[s]), ph);

        const uint32_t aB = sbase + s * STAGE_BYTES;
        const uint32_t bB = aB + 16384;

        LOAD_AFRAGS(0);
        LOAD_BFRAGS(0, 0, 0);
        LOAD_BFRAGS(1, 0, 1);
        MMA_GROUP(0, 0);
        LOAD_BFRAGS(0, 1, 0);
        MMA_GROUP(1, 1);
        LOAD_AFRAGS(1);
        LOAD_BFRAGS(1, 1, 1);
        // all smem reads of stage s are issued above; release-arrive now so
        // producers refill while the last two MMA groups run on registers.
        if (lane == 0) MBARRIER_ARRIVE(smem_u32(&s_empty[s]));
        MMA_GROUP(0, 0);
        MMA_GROUP(1, 1);
    }
#undef LOAD_BFRAGS
#undef MMA_GROUP
#undef LOAD_AFRAGS

    // epilogue
#pragma unroll
    for (int j = 0; j < 8; ++j) {
        const int col = n0 + wn + (j >> 2) * 32 + (j & 3) * 8 + 2 * cq;
        const float2 bv = *(const float2*)(bias + col);
#pragma unroll
        for (int ma = 0; ma < 2; ++ma) {
            const int row = m0 + wm + ma * 16 + r;
            float2 v0, v1;
            v0.x = acc[ma][j][0] + bv.x;
            v0.y = acc[ma][j][1] + bv.y;
            v1.x = acc[ma][j][2] + bv.x;
            v1.y = acc[ma][j][3] + bv.y;
            *(float2*)(C + (size_t)row * DMODEL + col)       = v0;
            *(float2*)(C + (size_t)(row + 8) * DMODEL + col) = v1;
        }
    }
}

// ---------------------------------------------------------------------------
// Attention (R10, near bandwidth bound)
// ---------------------------------------------------------------------------
#define AW 8
__global__ __launch_bounds__(32 * AW)
void attention_kernel(const float* __restrict__ q1, const float* __restrict__ k1,
                      const float* __restrict__ v1, const float* __restrict__ q2,
                      const float* __restrict__ k2, const float* __restrict__ v2,
                      __half* __restrict__ o1h, __half* __restrict__ o1l,
                      __half* __restrict__ o2h, __half* __restrict__ o2l)
{
    __shared__ float sq[2][AW][NHEADS][68];
    __shared__ float sk[2][AW][NHEADS][68];
    __shared__ float sv[2][AW][NHEADS][68];
    __shared__ float ss[AW][NHEADS][NHEADS];

    const int w = threadIdx.x >> 5;
    const int l = threadIdx.x & 31;
    const int s = blockIdx.x * AW + w;

    const float* Q[2] = { q1 + (size_t)s * DMODEL, q2 + (size_t)s * DMODEL };
    const float* K[2] = { k1 + (size_t)s * DMODEL, k2 + (size_t)s * DMODEL };
    const float* V[2] = { v1 + (size_t)s * DMODEL, v2 + (size_t)s * DMODEL };
    __half* OH[2] = { o1h + (size_t)s * DMODEL, o2h + (size_t)s * DMODEL };
    __half* OL[2] = { o1l + (size_t)s * DMODEL, o2l + (size_t)s * DMODEL };

    const int h0 = l >> 3;
    const int e0 = l & 7;

#pragma unroll
    for (int side = 0; side < 2; ++side) {
#pragma unroll
        for (int i = 0; i < 4; ++i) {
            const int idx = i * 32 + l;
            const int h = idx >> 4;
            const int d = (idx & 15) * 4;
            cp16(smem_u32(&sq[side][w][h][d]), Q[side] + idx * 4);
            cp16(smem_u32(&sk[side][w][h][d]), K[side] + idx * 4);
            cp16(smem_u32(&sv[side][w][h][d]), V[side] + idx * 4);
        }
        CP_COMMIT();
    }

#pragma unroll
    for (int side = 0; side < 2; ++side) {
        if (side == 0) cp_wait<1>(); else cp_wait<0>();
        __syncwarp();

        float s0 = 0.f, s1 = 0.f;
#pragma unroll
        for (int d4 = 0; d4 < 16; ++d4) {
            const float4 kk = *(const float4*)&sk[side][w][e0][d4 * 4];
            const float4 qa = *(const float4*)&sq[side][w][h0][d4 * 4];
            const float4 qb = *(const float4*)&sq[side][w][h0 + 4][d4 * 4];
            s0 = fmaf(qa.x, kk.x, s0); s0 = fmaf(qa.y, kk.y, s0);
            s0 = fmaf(qa.z, kk.z, s0); s0 = fmaf(qa.w, kk.w, s0);
            s1 = fmaf(qb.x, kk.x, s1); s1 = fmaf(qb.y, kk.y, s1);
            s1 = fmaf(qb.z, kk.z, s1); s1 = fmaf(qb.w, kk.w, s1);
        }
        s0 *= 0.125f;
        s1 *= 0.125f;

        float m0 = s0, m1 = s1;
#pragma unroll
        for (int d = 1; d < 8; d <<= 1) {
            m0 = fmaxf(m0, __shfl_xor_sync(0xFFFFFFFF, m0, d));
            m1 = fmaxf(m1, __shfl_xor_sync(0xFFFFFFFF, m1, d));
        }
        float x0 = expf(s0 - m0), x1 = expf(s1 - m1);
        float sum0 = x0, sum1 = x1;
#pragma unroll
        for (int d = 1; d < 8; d <<= 1) {
            sum0 += __shfl_xor_sync(0xFFFFFFFF, sum0, d);
            sum1 += __shfl_xor_sync(0xFFFFFFFF, sum1, d);
        }
        ss[w][h0][e0]     = x0 / sum0;
        ss[w][h0 + 4][e0] = x1 / sum1;
        __syncwarp();

#pragma unroll
        for (int dd = 0; dd < 2; ++dd) {
            const int d = l + dd * 32;
#pragma unroll
            for (int h = 0; h < NHEADS; ++h) {
                float a = 0.f;
#pragma unroll
                for (int e = 0; e < NHEADS; ++e)
                    a = fmaf(ss[w][h][e], sv[side][w][e][d], a);
                sq[side][w][h][d] = a;
            }
        }
        __syncwarp();

        __half2* oh2 = (__half2*)OH[side];
        __half2* ol2 = (__half2*)OL[side];
#pragma unroll
        for (int i = 0; i < 8; ++i) {
            const int j = i * 32 + l;
            const int h = j >> 5;
            const int d = (j & 31) * 2;
            const float a = sq[side][w][h][d];
            const float b = sq[side][w][h][d + 1];
            const __half2 hv = __floats2half2_rn(a, b);
            const float2 hf = __half22float2(hv);
            const __half2 lv = __floats2half2_rn(a - hf.x, b - hf.y);
            oh2[j] = hv;
            ol2[j] = lv;
        }
        __syncwarp();
    }
}

// ---------------------------------------------------------------------------
// kernel_launch
// ---------------------------------------------------------------------------
extern "C" void kernel_launch(void* const* d_in, const int* in_sizes, int n_in,
                              void* d_out, int out_size)
{
    const float* prot = (const float*)d_in[0];
    const float* lig  = (const float*)d_in[1];
    const float* Wq1 = (const float*)d_in[2];  const float* bq1 = (const float*)d_in[3];
    const float* Wk1 = (const float*)d_in[4];  const float* bk1 = (const float*)d_in[5];
    const float* Wv1 = (const float*)d_in[6];  const float* bv1 = (const float*)d_in[7];
    const float* Wq2 = (const float*)d_in[8];  const float* bq2 = (const float*)d_in[9];
    const float* Wk2 = (const float*)d_in[10]; const float* bk2 = (const float*)d_in[11];
    const float* Wv2 = (const float*)d_in[12]; const float* bv2 = (const float*)d_in[13];
    const float* Wo1 = (const float*)d_in[14]; const float* bo1 = (const float*)d_in[15];
    const float* Wo2 = (const float*)d_in[16]; const float* bo2 = (const float*)d_in[17];

    float* out      = (float*)d_out;
    float* prot_out = out;
    float* lig_out  = out + (size_t)NB * DMODEL;

    float *q1, *k1, *v1, *q2, *k2, *v2;
    cudaGetSymbolAddress((void**)&q1, g_q1);
    cudaGetSymbolAddress((void**)&k1, g_k1);
    cudaGetSymbolAddress((void**)&v1, g_v1);
    cudaGetSymbolAddress((void**)&q2, g_q2);
    cudaGetSymbolAddress((void**)&k2, g_k2);
    cudaGetSymbolAddress((void**)&v2, g_v2);

    __half *o1h, *o1l, *o2h, *o2l, *wh, *wl;
    cudaGetSymbolAddress((void**)&o1h, g_o1_h);
    cudaGetSymbolAddress((void**)&o1l, g_o1_l);
    cudaGetSymbolAddress((void**)&o2h, g_o2_h);
    cudaGetSymbolAddress((void**)&o2l, g_o2_l);
    cudaGetSymbolAddress((void**)&wh,  g_W_h);
    cudaGetSymbolAddress((void**)&wl,  g_W_l);

    // weight split (input split fused into proj producers)
    WSplit ws;
    ws.src[0] = Wq1; ws.src[1] = Wk1; ws.src[2] = Wv1; ws.src[3] = Wq2;
    ws.src[4] = Wk2; ws.src[5] = Wv2; ws.src[6] = Wo1; ws.src[7] = Wo2;
    split_w_kernel<<<dim3(128, 8), 256>>>(ws);

    const int DSM = NSTAGE * STAGE_BYTES;   // 196608
    cudaFuncSetAttribute(gemm_mma_kernel<true>,
                         cudaFuncAttributeMaxDynamicSharedMemorySize, DSM);
    cudaFuncSetAttribute(gemm_mma_kernel<false>,
                         cudaFuncAttributeMaxDynamicSharedMemorySize, DSM);

    const size_t WSZ = (size_t)DMODEL * DMODEL;
#define WH(i) (wh + (size_t)(i) * WSZ)
#define WL(i) (wl + (size_t)(i) * WSZ)

    // six input projections: A = fp32 inputs, split in-kernel (coalesced)
    GemmBatch pj = {};
    pj.Xf[0] = prot; pj.Wh[0] = WH(0); pj.Wl[0] = WL(0); pj.bias[0] = bq1; pj.C[0] = q1;
    pj.Xf[1] = lig;  pj.Wh[1] = WH(1); pj.Wl[1] = WL(1); pj.bias[1] = bk1; pj.C[1] = k1;
    pj.Xf[2] = lig;  pj.Wh[2] = WH(2); pj.Wl[2] = WL(2); pj.bias[2] = bv1; pj.C[2] = v1;
    pj.Xf[3] = lig;  pj.Wh[3] = WH(3); pj.Wl[3] = WL(3); pj.bias[3] = bq2; pj.C[3] = q2;
    pj.Xf[4] = prot; pj.Wh[4] = WH(4); pj.Wl[4] = WL(4); pj.bias[4] = bk2; pj.C[4] = k2;
    pj.Xf[5] = prot; pj.Wh[5] = WH(5); pj.Wl[5] = WL(5); pj.bias[5] = bv2; pj.C[5] = v2;

    dim3 gproj(DMODEL / BN, NB / BM, 6);
    gemm_mma_kernel<true><<<gproj, 384, DSM>>>(pj);

    attention_kernel<<<NB / AW, 32 * AW>>>(q1, k1, v1, q2, k2, v2, o1h, o1l, o2h, o2l);

    // output projections: A = attention hi/lo (pre-split by attention)
    GemmBatch op = {};
    op.Xh[0] = o1h; op.Xl[0] = o1l; op.Wh[0] = WH(6); op.Wl[0] = WL(6); op.bias[0] = bo1; op.C[0] = prot_out;
    op.Xh[1] = o2h; op.Xl[1] = o2l; op.Wh[1] = WH(7); op.Wl[1] = WL(7); op.bias[1] = bo2; op.C[1] = lig_out;
    for (int i = 2; i < 6; ++i) {
        op.Xh[i] = o1h; op.Xl[i] = o1l; op.Wh[i] = WH(6); op.Wl[i] = WL(6);
        op.bias[i] = bo1; op.C[i] = prot_out;
    }

    dim3 gout(DMODEL / BN, NB / BM, 2);
    gemm_mma_kernel<false><<<gout, 384, DSM>>>(op);
#undef WH
#undef WL
}

// round 17
// speedup vs baseline: 1.3460x; 1.0047x over previous
#include <cuda_runtime.h>
#include <cuda_fp16.h>
#include <cstdint>
#include <math.h>

#define NB     32768
#define DMODEL 512
#define NHEADS 8
#define DHEAD  64

// GEMM tiling (R13/R16 geometry — best known)
#define BM 128
#define BN 128
#define BK 32                 // K halves (or floats) per stage
#define NSTAGE 6
#define STAGE_BYTES 32768     // A 16KB + B 16KB (128 rows x 128B each)
#define NKT 16                // DMODEL / BK

// ---------------------------------------------------------------------------
// Scratch buffers
// ---------------------------------------------------------------------------
__device__ float g_q1[(size_t)NB * DMODEL];
__device__ float g_k1[(size_t)NB * DMODEL];
__device__ float g_v1[(size_t)NB * DMODEL];
__device__ float g_q2[(size_t)NB * DMODEL];
__device__ float g_k2[(size_t)NB * DMODEL];
__device__ float g_v2[(size_t)NB * DMODEL];

__device__ __half g_o1_h[(size_t)NB * DMODEL];
__device__ __half g_o1_l[(size_t)NB * DMODEL];
__device__ __half g_o2_h[(size_t)NB * DMODEL];
__device__ __half g_o2_l[(size_t)NB * DMODEL];
__device__ __half g_W_h[8][DMODEL * DMODEL];
__device__ __half g_W_l[8][DMODEL * DMODEL];

// ---------------------------------------------------------------------------
// helpers
// ---------------------------------------------------------------------------
__device__ __forceinline__ uint32_t smem_u32(const void* p) {
    uint32_t a;
    asm("{ .reg .u64 t; cvta.to.shared.u64 t, %1; cvt.u32.u64 %0, t; }"
        : "=r"(a) : "l"(p));
    return a;
}
__device__ __forceinline__ void cp16(uint32_t dst, const void* src) {
    asm volatile("cp.async.cg.shared.global [%0], [%1], 16;" :: "r"(dst), "l"(src));
}
#define CP_COMMIT() asm volatile("cp.async.commit_group;" ::: "memory")
template <int N> __device__ __forceinline__ void cp_wait() {
    asm volatile("cp.async.wait_group %0;" :: "n"(N) : "memory");
}
#define CP_WAIT_ALL() asm volatile("cp.async.wait_all;" ::: "memory")

#define MBARRIER_INIT(addr, cnt) \
    asm volatile("mbarrier.init.shared.b64 [%0], %1;" :: "r"(addr), "r"(cnt) : "memory")
#define MBARRIER_ARRIVE(addr) \
    asm volatile("mbarrier.arrive.release.cta.shared.b64 _, [%0];" :: "r"(addr) : "memory")
#define CP_ASYNC_MBARRIER_ARRIVE(addr) \
    asm volatile("cp.async.mbarrier.arrive.noinc.shared.b64 [%0];" :: "r"(addr) : "memory")

#define MBARRIER_WAIT_PARITY(addr, parity) do {                                   \
    uint32_t _m = (addr); uint32_t _p = (parity); uint32_t _d;                    \
    asm volatile(                                                                 \
        "{\n\t.reg .pred p;\n\t"                                                  \
        "mbarrier.try_wait.parity.acquire.cta.shared::cta.b64 p, [%1], %2;\n\t"   \
        "selp.b32 %0, 1, 0, p;\n\t}"                                              \
        : "=r"(_d) : "r"(_m), "r"(_p) : "memory");                                \
    if (!_d) {                                                                    \
        asm volatile(                                                             \
            "{\n\t.reg .pred P1;\n\t"                                             \
            "WL_%=:\n\t"                                                          \
            "mbarrier.try_wait.parity.acquire.cta.shared::cta.b64 P1, [%0], %1, 0x989680;\n\t" \
            "@P1 bra.uni WD_%=;\n\t"                                              \
            "bra.uni WL_%=;\n\t"                                                  \
            "WD_%=:\n\t}"                                                         \
            :: "r"(_m), "r"(_p) : "memory");                                      \
    } } while (0)

#define STS64(addr, v0, v1) \
    asm volatile("st.shared.v2.b32 [%0], {%1,%2};" \
                 :: "r"(addr), "r"(v0), "r"(v1) : "memory")

__device__ __forceinline__ void ldm_x4(uint32_t* d, uint32_t addr) {
    asm volatile("ldmatrix.sync.aligned.m8n8.x4.shared.b16 {%0,%1,%2,%3}, [%4];"
                 : "=r"(d[0]), "=r"(d[1]), "=r"(d[2]), "=r"(d[3]) : "r"(addr));
}

__device__ __forceinline__ void mma_f16(float* d, const uint32_t* a, const uint32_t* b) {
    asm volatile(
        "mma.sync.aligned.m16n8k16.row.col.f32.f16.f16.f32 "
        "{%0,%1,%2,%3}, {%4,%5,%6,%7}, {%8,%9}, {%0,%1,%2,%3};"
        : "+f"(d[0]), "+f"(d[1]), "+f"(d[2]), "+f"(d[3])
        : "r"(a[0]), "r"(a[1]), "r"(a[2]), "r"(a[3]), "r"(b[0]), "r"(b[1]));
}

__device__ __forceinline__ uint32_t h2u(__half2 h) {
    return *(uint32_t*)&h;
}

// ---------------------------------------------------------------------------
// Weight split kernel
// ---------------------------------------------------------------------------
struct WSplit { const float* src[8]; };

__global__ __launch_bounds__(256)
void split_w_kernel(WSplit ws)
{
    const int z = blockIdx.y;
    const float2* src = (const float2*)ws.src[z];
    __half2* hi = (__half2*)&g_W_h[z][0];
    __half2* lo = (__half2*)&g_W_l[z][0];
    const int n2 = DMODEL * DMODEL / 2;
    for (int i = blockIdx.x * blockDim.x + threadIdx.x; i < n2;
         i += gridDim.x * blockDim.x) {
        float2 v = src[i];
        __half2 h = __floats2half2_rn(v.x, v.y);
        float2 hb = __half22float2(h);
        __half2 l = __floats2half2_rn(v.x - hb.x, v.y - hb.y);
        hi[i] = h;
        lo[i] = l;
    }
}

// ---------------------------------------------------------------------------
// Warp-specialized split-fp16 GEMM: C = X @ W^T + bias
//   FUSE_SPLIT_A=true : A fp32, split in producers; single merged `full`
//     barrier (count 256 = 128 cp.async noinc arrivals + 128 STS arrives)
//     -> ONE consumer wait per k-tile.
//   FUSE_SPLIT_A=false: A and B pre-split fp16 via cp.async; `full` barrier
//     count 128 (cp.async noinc only) -> one wait, as before.
//   Early empty-arrive after last ldmatrix (R16 win).
// ---------------------------------------------------------------------------
struct GemmBatch {
    const float*  Xf[6];
    const __half* Xh[6];
    const __half* Xl[6];
    const __half* Wh[6];
    const __half* Wl[6];
    const float*  bias[6];
    float*        C[6];
};

template <bool FUSE_SPLIT_A>
__global__ __launch_bounds__(384, 1)
void gemm_mma_kernel(GemmBatch args)
{
    const int z = blockIdx.z;
    const float*  __restrict__ bias = args.bias[z];
    float*        __restrict__ C    = args.C[z];

    const int n0 = blockIdx.x * BN;
    const int m0 = blockIdx.y * BM;

    extern __shared__ __align__(128) char smraw[];
    const uint32_t sbase = smem_u32(smraw);

    __shared__ __align__(8) uint64_t s_full[NSTAGE], s_empty[NSTAGE];

    const int tid  = threadIdx.x;
    const int wid  = tid >> 5;
    const int lane = tid & 31;

    if (tid == 0) {
#pragma unroll
        for (int s = 0; s < NSTAGE; ++s) {
            // FUSE: 128 noinc (B cp.async) + 128 thread arrives (A STS)
            MBARRIER_INIT(smem_u32(&s_full[s]), FUSE_SPLIT_A ? 256 : 128);
            MBARRIER_INIT(smem_u32(&s_empty[s]), 8);
        }
    }
    __syncthreads();

    if (wid >= 8) {
        // ================= PRODUCER (warps 8-11, 128 threads) =================
        const __half* __restrict__ Wh = args.Wh[z];
        const __half* __restrict__ Wl = args.Wl[z];
        const int ptid = tid - 256;   // 0..127

        if (FUSE_SPLIT_A) {
            const float* __restrict__ Xf = args.Xf[z];
#pragma unroll
            for (int kt = 0; kt < NKT; ++kt) {
                const int s = kt % NSTAGE;
                // coalesced A loads: 8 thr/row, consecutive 16B chunks
                float4 av[8];
#pragma unroll
                for (int j = 0; j < 8; ++j) {
                    const int idx = ptid + j * 128;
                    const int row = idx >> 3, c = idx & 7;
                    av[j] = *(const float4*)(Xf + (size_t)(m0 + row) * DMODEL
                                             + kt * BK + c * 4);
                }
                if (kt >= NSTAGE) {
                    MBARRIER_WAIT_PARITY(smem_u32(&s_empty[s]),
                                         (uint32_t)(((kt - NSTAGE) / NSTAGE) & 1));
                }
                const uint32_t st = sbase + s * STAGE_BYTES;
                const size_t koff = (size_t)kt * BK;

                // B via cp.async -> noinc arrival on merged full barrier
#pragma unroll
                for (int j = 0; j < 8; ++j) {
                    const int idx = ptid + j * 128;
                    const int row = idx >> 3, c = idx & 7;
                    const __half* src = (c < 4) ? Wh : Wl;
                    cp16(st + 16384 + row * 128 + ((c ^ (row & 7)) << 4),
                         src + (size_t)(n0 + row) * DMODEL + koff + (c & 3) * 8);
                }
                CP_ASYNC_MBARRIER_ARRIVE(smem_u32(&s_full[s]));

                // A: convert fp32 -> hi/lo, STS.64, then thread-arrive (release)
#pragma unroll
                for (int j = 0; j < 8; ++j) {
                    const int idx = ptid + j * 128;
                    const int row = idx >> 3, c = idx & 7;
                    const int sw = row & 7;
                    const float4 a = av[j];
                    const __half2 h0 = __floats2half2_rn(a.x, a.y);
                    const __half2 h1 = __floats2half2_rn(a.z, a.w);
                    const float2 f0 = __half22float2(h0), f1 = __half22float2(h1);
                    const __half2 l0 = __floats2half2_rn(a.x - f0.x, a.y - f0.y);
                    const __half2 l1 = __floats2half2_rn(a.z - f1.x, a.w - f1.y);
                    const uint32_t rowb = st + row * 128 + ((c & 1) << 3);
                    STS64(rowb + ((((c >> 1)    ) ^ sw) << 4), h2u(h0), h2u(h1));
                    STS64(rowb + ((((c >> 1) + 4) ^ sw) << 4), h2u(l0), h2u(l1));
                }
                MBARRIER_ARRIVE(smem_u32(&s_full[s]));
            }
        } else {
            const __half* __restrict__ Xh = args.Xh[z];
            const __half* __restrict__ Xl = args.Xl[z];
#pragma unroll
            for (int kt = 0; kt < NKT; ++kt) {
                const int s = kt % NSTAGE;
                if (kt >= NSTAGE) {
                    MBARRIER_WAIT_PARITY(smem_u32(&s_empty[s]),
                                         (uint32_t)(((kt - NSTAGE) / NSTAGE) & 1));
                }
                const uint32_t st = sbase + s * STAGE_BYTES;
                const size_t koff = (size_t)kt * BK;
#pragma unroll
                for (int j = 0; j < 8; ++j) {
                    const int idx = ptid + j * 128;
                    const int row = idx >> 3, c = idx & 7;
                    const __half* src = (c < 4) ? Xh : Xl;
                    cp16(st + row * 128 + ((c ^ (row & 7)) << 4),
                         src + (size_t)(m0 + row) * DMODEL + koff + (c & 3) * 8);
                }
#pragma unroll
                for (int j = 0; j < 8; ++j) {
                    const int idx = ptid + j * 128;
                    const int row = idx >> 3, c = idx & 7;
                    const __half* src = (c < 4) ? Wh : Wl;
                    cp16(st + 16384 + row * 128 + ((c ^ (row & 7)) << 4),
                         src + (size_t)(n0 + row) * DMODEL + koff + (c & 3) * 8);
                }
                CP_ASYNC_MBARRIER_ARRIVE(smem_u32(&s_full[s]));
            }
        }
        CP_WAIT_ALL();
        return;
    }

    // =================== CONSUMER (warps 0-7, 256 threads) ===================
    const int r  = lane >> 2;
    const int cq = lane & 3;
    const int wm = (wid >> 1) * 32;
    const int wn = (wid & 1) * 64;

    const int a_row_in16 = (lane & 7) + ((lane >> 3) & 1) * 8;
    const int a_kh       = lane >> 4;
    const int b_row_in16 = (lane & 7) + ((lane >> 4) & 1) * 8;
    const int b_kh       = (lane >> 3) & 1;

    float acc[2][8][4];
#pragma unroll
    for (int i = 0; i < 2; ++i)
#pragma unroll
        for (int j = 0; j < 8; ++j)
#pragma unroll
            for (int k = 0; k < 4; ++k)
                acc[i][j][k] = 0.f;

#define LOAD_BFRAGS(bu, ksv, grpv) do {                                         \
        _Pragma("unroll")                                                       \
        for (int pair = 0; pair < 2; ++pair) {                                  \
            const int brow = wn + (grpv) * 32 + pair * 16 + b_row_in16;         \
            const int sw = brow & 7;                                            \
            const uint32_t rb = bB + brow * 128;                                \
            uint32_t th[4], tl[4];                                              \
            ldm_x4(th, rb + (((2 * (ksv) + b_kh) ^ sw) << 4));                  \
            ldm_x4(tl, rb + (((2 * (ksv) + b_kh + 4) ^ sw) << 4));              \
            bhb[bu][pair * 2 + 0][0] = th[0]; bhb[bu][pair * 2 + 0][1] = th[1]; \
            bhb[bu][pair * 2 + 1][0] = th[2]; bhb[bu][pair * 2 + 1][1] = th[3]; \
            blb[bu][pair * 2 + 0][0] = tl[0]; blb[bu][pair * 2 + 0][1] = tl[1]; \
            blb[bu][pair * 2 + 1][0] = tl[2]; blb[bu][pair * 2 + 1][1] = tl[3]; \
        }                                                                       \
    } while (0)

#define MMA_GROUP(bu, grpv) do {                                                \
        _Pragma("unroll")                                                       \
        for (int i = 0; i < 4; ++i) {                                           \
            mma_f16(acc[0][(grpv) * 4 + i], ah[0], bhb[bu][i]);                 \
            mma_f16(acc[1][(grpv) * 4 + i], ah[1], bhb[bu][i]);                 \
        }                                                                       \
        _Pragma("unroll")                                                       \
        for (int i = 0; i < 4; ++i) {                                           \
            mma_f16(acc[0][(grpv) * 4 + i], ah[0], blb[bu][i]);                 \
            mma_f16(acc[1][(grpv) * 4 + i], ah[1], blb[bu][i]);                 \
        }                                                                       \
        _Pragma("unroll")                                                       \
        for (int i = 0; i < 4; ++i) {                                           \
            mma_f16(acc[0][(grpv) * 4 + i], al[0], bhb[bu][i]);                 \
            mma_f16(acc[1][(grpv) * 4 + i], al[1], bhb[bu][i]);                 \
        }                                                                       \
    } while (0)

#define LOAD_AFRAGS(ksv) do {                                                   \
        _Pragma("unroll")                                                       \
        for (int ma = 0; ma < 2; ++ma) {                                        \
            const int arow = wm + ma * 16 + a_row_in16;                         \
            const int sw = arow & 7;                                            \
            const uint32_t rb = aB + arow * 128;                                \
            ldm_x4(ah[ma], rb + (((2 * (ksv) + a_kh) ^ sw) << 4));              \
            ldm_x4(al[ma], rb + (((2 * (ksv) + a_kh + 4) ^ sw) << 4));          \
        }                                                                       \
    } while (0)

    uint32_t bhb[2][4][2], blb[2][4][2];
    uint32_t ah[2][4], al[2][4];

#pragma unroll
    for (int kt = 0; kt < NKT; ++kt) {
        const int s = kt % NSTAGE;
        const uint32_t ph = (uint32_t)((kt / NSTAGE) & 1);
        MBARRIER_WAIT_PARITY(smem_u32(&s_full[s]), ph);   // single wait

        const uint32_t aB = sbase + s * STAGE_BYTES;
        const uint32_t bB = aB + 16384;

        LOAD_AFRAGS(0);
        LOAD_BFRAGS(0, 0, 0);
        LOAD_BFRAGS(1, 0, 1);
        MMA_GROUP(0, 0);
        LOAD_BFRAGS(0, 1, 0);
        MMA_GROUP(1, 1);
        LOAD_AFRAGS(1);
        LOAD_BFRAGS(1, 1, 1);
        // all smem reads of stage s issued; release-arrive so producers refill
        // while the last two MMA groups run on registers.
        if (lane == 0) MBARRIER_ARRIVE(smem_u32(&s_empty[s]));
        MMA_GROUP(0, 0);
        MMA_GROUP(1, 1);
    }
#undef LOAD_BFRAGS
#undef MMA_GROUP
#undef LOAD_AFRAGS

    // epilogue
#pragma unroll
    for (int j = 0; j < 8; ++j) {
        const int col = n0 + wn + (j >> 2) * 32 + (j & 3) * 8 + 2 * cq;
        const float2 bv = *(const float2*)(bias + col);
#pragma unroll
        for (int ma = 0; ma < 2; ++ma) {
            const int row = m0 + wm + ma * 16 + r;
            float2 v0, v1;
            v0.x = acc[ma][j][0] + bv.x;
            v0.y = acc[ma][j][1] + bv.y;
            v1.x = acc[ma][j][2] + bv.x;
            v1.y = acc[ma][j][3] + bv.y;
            *(float2*)(C + (size_t)row * DMODEL + col)       = v0;
            *(float2*)(C + (size_t)(row + 8) * DMODEL + col) = v1;
        }
    }
}

// ---------------------------------------------------------------------------
// Attention (R10, near bandwidth bound)
// ---------------------------------------------------------------------------
#define AW 8
__global__ __launch_bounds__(32 * AW)
void attention_kernel(const float* __restrict__ q1, const float* __restrict__ k1,
                      const float* __restrict__ v1, const float* __restrict__ q2,
                      const float* __restrict__ k2, const float* __restrict__ v2,
                      __half* __restrict__ o1h, __half* __restrict__ o1l,
                      __half* __restrict__ o2h, __half* __restrict__ o2l)
{
    __shared__ float sq[2][AW][NHEADS][68];
    __shared__ float sk[2][AW][NHEADS][68];
    __shared__ float sv[2][AW][NHEADS][68];
    __shared__ float ss[AW][NHEADS][NHEADS];

    const int w = threadIdx.x >> 5;
    const int l = threadIdx.x & 31;
    const int s = blockIdx.x * AW + w;

    const float* Q[2] = { q1 + (size_t)s * DMODEL, q2 + (size_t)s * DMODEL };
    const float* K[2] = { k1 + (size_t)s * DMODEL, k2 + (size_t)s * DMODEL };
    const float* V[2] = { v1 + (size_t)s * DMODEL, v2 + (size_t)s * DMODEL };
    __half* OH[2] = { o1h + (size_t)s * DMODEL, o2h + (size_t)s * DMODEL };
    __half* OL[2] = { o1l + (size_t)s * DMODEL, o2l + (size_t)s * DMODEL };

    const int h0 = l >> 3;
    const int e0 = l & 7;

#pragma unroll
    for (int side = 0; side < 2; ++side) {
#pragma unroll
        for (int i = 0; i < 4; ++i) {
            const int idx = i * 32 + l;
            const int h = idx >> 4;
            const int d = (idx & 15) * 4;
            cp16(smem_u32(&sq[side][w][h][d]), Q[side] + idx * 4);
            cp16(smem_u32(&sk[side][w][h][d]), K[side] + idx * 4);
            cp16(smem_u32(&sv[side][w][h][d]), V[side] + idx * 4);
        }
        CP_COMMIT();
    }

#pragma unroll
    for (int side = 0; side < 2; ++side) {
        if (side == 0) cp_wait<1>(); else cp_wait<0>();
        __syncwarp();

        float s0 = 0.f, s1 = 0.f;
#pragma unroll
        for (int d4 = 0; d4 < 16; ++d4) {
            const float4 kk = *(const float4*)&sk[side][w][e0][d4 * 4];
            const float4 qa = *(const float4*)&sq[side][w][h0][d4 * 4];
            const float4 qb = *(const float4*)&sq[side][w][h0 + 4][d4 * 4];
            s0 = fmaf(qa.x, kk.x, s0); s0 = fmaf(qa.y, kk.y, s0);
            s0 = fmaf(qa.z, kk.z, s0); s0 = fmaf(qa.w, kk.w, s0);
            s1 = fmaf(qb.x, kk.x, s1); s1 = fmaf(qb.y, kk.y, s1);
            s1 = fmaf(qb.z, kk.z, s1); s1 = fmaf(qb.w, kk.w, s1);
        }
        s0 *= 0.125f;
        s1 *= 0.125f;

        float m0 = s0, m1 = s1;
#pragma unroll
        for (int d = 1; d < 8; d <<= 1) {
            m0 = fmaxf(m0, __shfl_xor_sync(0xFFFFFFFF, m0, d));
            m1 = fmaxf(m1, __shfl_xor_sync(0xFFFFFFFF, m1, d));
        }
        float x0 = expf(s0 - m0), x1 = expf(s1 - m1);
        float sum0 = x0, sum1 = x1;
#pragma unroll
        for (int d = 1; d < 8; d <<= 1) {
            sum0 += __shfl_xor_sync(0xFFFFFFFF, sum0, d);
            sum1 += __shfl_xor_sync(0xFFFFFFFF, sum1, d);
        }
        ss[w][h0][e0]     = x0 / sum0;
        ss[w][h0 + 4][e0] = x1 / sum1;
        __syncwarp();

#pragma unroll
        for (int dd = 0; dd < 2; ++dd) {
            const int d = l + dd * 32;
#pragma unroll
            for (int h = 0; h < NHEADS; ++h) {
                float a = 0.f;
#pragma unroll
                for (int e = 0; e < NHEADS; ++e)
                    a = fmaf(ss[w][h][e], sv[side][w][e][d], a);
                sq[side][w][h][d] = a;
            }
        }
        __syncwarp();

        __half2* oh2 = (__half2*)OH[side];
        __half2* ol2 = (__half2*)OL[side];
#pragma unroll
        for (int i = 0; i < 8; ++i) {
            const int j = i * 32 + l;
            const int h = j >> 5;
            const int d = (j & 31) * 2;
            const float a = sq[side][w][h][d];
            const float b = sq[side][w][h][d + 1];
            const __half2 hv = __floats2half2_rn(a, b);
            const float2 hf = __half22float2(hv);
            const __half2 lv = __floats2half2_rn(a - hf.x, b - hf.y);
            oh2[j] = hv;
            ol2[j] = lv;
        }
        __syncwarp();
    }
}

// ---------------------------------------------------------------------------
// kernel_launch
// ---------------------------------------------------------------------------
extern "C" void kernel_launch(void* const* d_in, const int* in_sizes, int n_in,
                              void* d_out, int out_size)
{
    const float* prot = (const float*)d_in[0];
    const float* lig  = (const float*)d_in[1];
    const float* Wq1 = (const float*)d_in[2];  const float* bq1 = (const float*)d_in[3];
    const float* Wk1 = (const float*)d_in[4];  const float* bk1 = (const float*)d_in[5];
    const float* Wv1 = (const float*)d_in[6];  const float* bv1 = (const float*)d_in[7];
    const float* Wq2 = (const float*)d_in[8];  const float* bq2 = (const float*)d_in[9];
    const float* Wk2 = (const float*)d_in[10]; const float* bk2 = (const float*)d_in[11];
    const float* Wv2 = (const float*)d_in[12]; const float* bv2 = (const float*)d_in[13];
    const float* Wo1 = (const float*)d_in[14]; const float* bo1 = (const float*)d_in[15];
    const float* Wo2 = (const float*)d_in[16]; const float* bo2 = (const float*)d_in[17];

    float* out      = (float*)d_out;
    float* prot_out = out;
    float* lig_out  = out + (size_t)NB * DMODEL;

    float *q1, *k1, *v1, *q2, *k2, *v2;
    cudaGetSymbolAddress((void**)&q1, g_q1);
    cudaGetSymbolAddress((void**)&k1, g_k1);
    cudaGetSymbolAddress((void**)&v1, g_v1);
    cudaGetSymbolAddress((void**)&q2, g_q2);
    cudaGetSymbolAddress((void**)&k2, g_k2);
    cudaGetSymbolAddress((void**)&v2, g_v2);

    __half *o1h, *o1l, *o2h, *o2l, *wh, *wl;
    cudaGetSymbolAddress((void**)&o1h, g_o1_h);
    cudaGetSymbolAddress((void**)&o1l, g_o1_l);
    cudaGetSymbolAddress((void**)&o2h, g_o2_h);
    cudaGetSymbolAddress((void**)&o2l, g_o2_l);
    cudaGetSymbolAddress((void**)&wh,  g_W_h);
    cudaGetSymbolAddress((void**)&wl,  g_W_l);

    // weight split (input split fused into proj producers)
    WSplit ws;
    ws.src[0] = Wq1; ws.src[1] = Wk1; ws.src[2] = Wv1; ws.src[3] = Wq2;
    ws.src[4] = Wk2; ws.src[5] = Wv2; ws.src[6] = Wo1; ws.src[7] = Wo2;
    split_w_kernel<<<dim3(128, 8), 256>>>(ws);

    const int DSM = NSTAGE * STAGE_BYTES;   // 196608
    cudaFuncSetAttribute(gemm_mma_kernel<true>,
                         cudaFuncAttributeMaxDynamicSharedMemorySize, DSM);
    cudaFuncSetAttribute(gemm_mma_kernel<false>,
                         cudaFuncAttributeMaxDynamicSharedMemorySize, DSM);

    const size_t WSZ = (size_t)DMODEL * DMODEL;
#define WH(i) (wh + (size_t)(i) * WSZ)
#define WL(i) (wl + (size_t)(i) * WSZ)

    // six input projections: A = fp32 inputs, split in-kernel (coalesced)
    GemmBatch pj = {};
    pj.Xf[0] = prot; pj.Wh[0] = WH(0); pj.Wl[0] = WL(0); pj.bias[0] = bq1; pj.C[0] = q1;
    pj.Xf[1] = lig;  pj.Wh[1] = WH(1); pj.Wl[1] = WL(1); pj.bias[1] = bk1; pj.C[1] = k1;
    pj.Xf[2] = lig;  pj.Wh[2] = WH(2); pj.Wl[2] = WL(2); pj.bias[2] = bv1; pj.C[2] = v1;
    pj.Xf[3] = lig;  pj.Wh[3] = WH(3); pj.Wl[3] = WL(3); pj.bias[3] = bq2; pj.C[3] = q2;
    pj.Xf[4] = prot; pj.Wh[4] = WH(4); pj.Wl[4] = WL(4); pj.bias[4] = bk2; pj.C[4] = k2;
    pj.Xf[5] = prot; pj.Wh[5] = WH(5); pj.Wl[5] = WL(5); pj.bias[5] = bv2; pj.C[5] = v2;

    dim3 gproj(DMODEL / BN, NB / BM, 6);
    gemm_mma_kernel<true><<<gproj, 384, DSM>>>(pj);

    attention_kernel<<<NB / AW, 32 * AW>>>(q1, k1, v1, q2, k2, v2, o1h, o1l, o2h, o2l);

    // output projections: A = attention hi/lo (pre-split by attention)
    GemmBatch op = {};
    op.Xh[0] = o1h; op.Xl[0] = o1l; op.Wh[0] = WH(6); op.Wl[0] = WL(6); op.bias[0] = bo1; op.C[0] = prot_out;
    op.Xh[1] = o2h; op.Xl[1] = o2l; op.Wh[1] = WH(7); op.Wl[1] = WL(7); op.bias[1] = bo2; op.C[1] = lig_out;
    for (int i = 2; i < 6; ++i) {
        op.Xh[i] = o1h; op.Xl[i] = o1l; op.Wh[i] = WH(6); op.Wl[i] = WL(6);
        op.bias[i] = bo1; op.C[i] = prot_out;
    }

    dim3 gout(DMODEL / BN, NB / BM, 2);
    gemm_mma_kernel<false><<<gout, 384, DSM>>>(op);
#undef WH
#undef WL
}